// round 14
// baseline (speedup 1.0000x reference)
#include <cuda_runtime.h>
#include <cstdint>

// InstantNGP: hash-grid encode + MLP 32->64->64->3 via warp-level fp16 mma.sync
// m16n8k16 (f32 accumulate). Round-14 = R12 base with:
//  - TPW 4 / GRID 4096: wave quantization fix (3.46 -> 6.92 waves, ~1% tail)
//  - layer-0 B frags as [nt][lane] uint4: one LDS.128 per nt (from R13)
//  - layer-1 B frags back in SMEM (R12 style; R13's register residency hurt)

namespace {

constexpr int S_DIM   = 1024;
constexpr int NPTS    = S_DIM * S_DIM;
constexpr int TBL     = 1 << 19;

constexpr int WARPS   = 4;
constexpr int THREADS = WARPS * 32;
constexpr int TILE    = 16;               // points per warp-tile
constexpr int TPW     = 4;                // tiles per warp
constexpr int PPW     = TILE * TPW;       // 64 points per warp
constexpr int GRID    = NPTS / (PPW * WARPS);   // 4096
constexpr int ESTRIDE = 20;               // uint32 per enc row (swizzled, conflict-free)
constexpr float ESCALE   = 256.0f;        // 2^8: lift enc out of fp16 subnormal range
constexpr float ESCALE_I = 1.0f / 256.0f;

__device__ __forceinline__ uint32_t f16x2(float lo, float hi) {
    uint32_t r;
    asm("cvt.rn.f16x2.f32 %0, %1, %2;" : "=r"(r) : "f"(hi), "f"(lo));
    return r;
}

__device__ __forceinline__ int eidx(int row, int col) {
    return row * ESTRIDE + (col ^ ((row >> 3) << 1));
}

__device__ __forceinline__ void mma16(float* d,
                                      uint32_t a0, uint32_t a1, uint32_t a2, uint32_t a3,
                                      uint32_t b0, uint32_t b1) {
    asm volatile(
        "mma.sync.aligned.m16n8k16.row.col.f32.f16.f16.f32 "
        "{%0,%1,%2,%3},{%4,%5,%6,%7},{%8,%9},{%0,%1,%2,%3};"
        : "+f"(d[0]), "+f"(d[1]), "+f"(d[2]), "+f"(d[3])
        : "r"(a0), "r"(a1), "r"(a2), "r"(a3), "r"(b0), "r"(b1));
}

__global__ __launch_bounds__(THREADS, 5) void ngp_mma_kernel(
    const float2* __restrict__ xy,
    const float2* __restrict__ tab,
    const float*  __restrict__ W0,     // (32, 64) [k][n]
    const float*  __restrict__ W1,     // (64, 64) [k][n]
    const float*  __restrict__ W2,     // (64, 3)
    float*        __restrict__ out)    // (3, S, S)
{
    __shared__ uint4    w0q[8][32];                    // 4 KB  B frags layer0: [nt][lane] = kk0|kk1
    __shared__ uint2    w1f[4 * 8 * 32];               // 8 KB  B frags layer1
    __shared__ float    w2s[3 * 64];                   // packed [j][c], pre-scaled
    __shared__ uint32_t scratch[WARPS][TILE * ESTRIDE];  // 5 KB enc (fp16x2)

    const int tid = threadIdx.x;

    // ---- stage weights in fragment order (once per CTA) ----
    for (int i = tid; i < 8 * 32; i += THREADS) {
        const int nt = i >> 5, ln = i & 31;
        const int t = ln & 3, g = ln >> 2, n = nt * 8 + g;
        uint32_t v[4];
#pragma unroll
        for (int kk = 0; kk < 2; kk++) {
            const int kb = 16 * kk + 2 * t;
            v[2 * kk]     = f16x2(W0[kb * 64 + n],       W0[(kb + 1) * 64 + n]);
            v[2 * kk + 1] = f16x2(W0[(kb + 8) * 64 + n], W0[(kb + 9) * 64 + n]);
        }
        w0q[nt][ln] = make_uint4(v[0], v[1], v[2], v[3]);
    }
    for (int i = tid; i < 4 * 8 * 32; i += THREADS) {
        const int kk = i >> 8, nt = (i >> 5) & 7, ln = i & 31;
        const int t = ln & 3, g = ln >> 2, n = nt * 8 + g;
        const int kb = 16 * kk + 2 * t;
        w1f[i] = make_uint2(f16x2(W1[kb * 64 + n],       W1[(kb + 1) * 64 + n]),
                            f16x2(W1[(kb + 8) * 64 + n], W1[(kb + 9) * 64 + n]));
    }
    for (int i = tid; i < 3 * 64; i += THREADS) {
        const int j = i >> 6, c = i & 63;
        w2s[i] = W2[c * 3 + j] * ESCALE_I;   // undo enc scaling here
    }
    __syncthreads();

    const int wid  = tid >> 5;
    const int lane = tid & 31;
    const int t    = lane & 3;          // threadIDInGroup
    const int g    = lane >> 2;         // groupID (row within 8)
    const int h    = lane >> 4;         // level parity for encode
    const int pl   = lane & 15;         // point within tile for encode
    uint32_t* buf  = scratch[wid];
    const int wg   = blockIdx.x * WARPS + wid;

    // floor(16 * 1.5^l): even levels / odd levels
    const int res_e[8] = {16, 36, 81, 182, 410, 922, 2075, 4670};
    const int res_o[8] = {24, 54, 121, 273, 615, 1383, 3113, 7006};

    for (int tile = 0; tile < TPW; tile++) {
        const int tb = wg * PPW + tile * TILE;
        __syncwarp();

        // ---- encode: point pl, levels 2*lp + h; store fp16x2 (f0,f1)*2^8 ----
        const float2 p = __ldg(&xy[tb + pl]);
        const float c0 = p.x, c1 = p.y;
#pragma unroll
        for (int lp = 0; lp < 8; lp++) {
            const int res   = h ? res_o[lp] : res_e[lp];
            const int level = 2 * lp + h;
            const bool dense = (lp < 5);   // levels 0..9 dense, 10..15 hashed

            const float fres = (float)res;
            const float px = c0 * fres;
            const float py = c1 * fres;
            const float fx = floorf(px);
            const float fy = floorf(py);
            const float wx = px - fx;
            const float wy = py - fy;
            const int ix = (int)fx;
            const int iy = (int)fy;

            int i00, i01, i10, i11;
            if (dense) {
                const int r1 = res + 1;
                i00 = ix + iy * r1;
                i01 = i00 + r1;
                i10 = i00 + 1;
                i11 = i01 + 1;
            } else {
                const uint32_t P = 2654435761u;
                const uint32_t ux = (uint32_t)ix;
                const uint32_t uy = (uint32_t)iy;
                const uint32_t hy0 = uy * P;
                const uint32_t hy1 = (uy + 1u) * P;
                i00 = (int)((ux        ^ hy0) & (uint32_t)(TBL - 1));
                i01 = (int)((ux        ^ hy1) & (uint32_t)(TBL - 1));
                i10 = (int)(((ux + 1u) ^ hy0) & (uint32_t)(TBL - 1));
                i11 = (int)(((ux + 1u) ^ hy1) & (uint32_t)(TBL - 1));
            }

            const float2* lt = tab + (size_t)level * TBL;
            const float2 a00 = __ldg(lt + i00);
            const float2 a01 = __ldg(lt + i01);
            const float2 a10 = __ldg(lt + i10);
            const float2 a11 = __ldg(lt + i11);

            const float w00 = (1.0f - wx) * (1.0f - wy);
            const float w01 = (1.0f - wx) * wy;
            const float w10 = wx * (1.0f - wy);
            const float w11 = wx * wy;

            const float f0 = a00.x * w00 + a01.x * w01 + a10.x * w10 + a11.x * w11;
            const float f1 = a00.y * w00 + a01.y * w01 + a10.y * w10 + a11.y * w11;

            buf[eidx(pl, level)] = f16x2(f0 * ESCALE, f1 * ESCALE);
        }
        __syncwarp();

        // ---- layer 0: (16x32) @ (32x64), m16n8k16, one LDS.128 per nt ----
        float C[8][4];
#pragma unroll
        for (int nt = 0; nt < 8; nt++)
#pragma unroll
            for (int j = 0; j < 4; j++) C[nt][j] = 0.0f;

        {
            const uint32_t a0k0 = buf[eidx(g,     t)];
            const uint32_t a1k0 = buf[eidx(g + 8, t)];
            const uint32_t a2k0 = buf[eidx(g,     t + 4)];
            const uint32_t a3k0 = buf[eidx(g + 8, t + 4)];
            const uint32_t a0k1 = buf[eidx(g,     8 + t)];
            const uint32_t a1k1 = buf[eidx(g + 8, 8 + t)];
            const uint32_t a2k1 = buf[eidx(g,     8 + t + 4)];
            const uint32_t a3k1 = buf[eidx(g + 8, 8 + t + 4)];
#pragma unroll
            for (int nt = 0; nt < 8; nt++) {
                const uint4 b = w0q[nt][lane];
                mma16(C[nt], a0k0, a1k0, a2k0, a3k0, b.x, b.y);
                mma16(C[nt], a0k1, a1k1, a2k1, a3k1, b.z, b.w);
            }
        }

        // ---- pack all layer-1 A fragments (C dies here) ----
        uint32_t A[4][4];
#pragma unroll
        for (int kk = 0; kk < 4; kk++) {
            A[kk][0] = f16x2(fmaxf(C[2 * kk][0], 0.0f),     fmaxf(C[2 * kk][1], 0.0f));
            A[kk][1] = f16x2(fmaxf(C[2 * kk][2], 0.0f),     fmaxf(C[2 * kk][3], 0.0f));
            A[kk][2] = f16x2(fmaxf(C[2 * kk + 1][0], 0.0f), fmaxf(C[2 * kk + 1][1], 0.0f));
            A[kk][3] = f16x2(fmaxf(C[2 * kk + 1][2], 0.0f), fmaxf(C[2 * kk + 1][3], 0.0f));
        }

        // ---- layer 1 (nt-outer) fused with epilogue: 4-reg accumulator ----
        float acc[2][3] = {{0.f, 0.f, 0.f}, {0.f, 0.f, 0.f}};
#pragma unroll
        for (int nt = 0; nt < 8; nt++) {
            float C1[4] = {0.f, 0.f, 0.f, 0.f};
#pragma unroll
            for (int kk = 0; kk < 4; kk++) {
                const uint2 b = w1f[(kk * 8 + nt) * 32 + lane];
                mma16(C1, A[kk][0], A[kk][1], A[kk][2], A[kk][3], b.x, b.y);
            }
            const int cA = nt * 8 + 2 * t;
            float2 w[3];
#pragma unroll
            for (int j = 0; j < 3; j++)
                w[j] = *reinterpret_cast<const float2*>(&w2s[j * 64 + cA]);
            const float vA0 = fmaxf(C1[0], 0.0f);
            const float vB0 = fmaxf(C1[1], 0.0f);
            const float vA1 = fmaxf(C1[2], 0.0f);
            const float vB1 = fmaxf(C1[3], 0.0f);
#pragma unroll
            for (int j = 0; j < 3; j++) {
                acc[0][j] += vA0 * w[j].x + vB0 * w[j].y;
                acc[1][j] += vA1 * w[j].x + vB1 * w[j].y;
            }
        }
#pragma unroll
        for (int r = 0; r < 2; r++)
#pragma unroll
            for (int j = 0; j < 3; j++) {
                float v = acc[r][j];
                v += __shfl_xor_sync(0xffffffffu, v, 1);
                v += __shfl_xor_sync(0xffffffffu, v, 2);
                acc[r][j] = v;
            }
        if (t == 0) {
#pragma unroll
            for (int r = 0; r < 2; r++) {
                const int pid = tb + g + 8 * r;
#pragma unroll
                for (int j = 0; j < 3; j++) out[j * NPTS + pid] = acc[r][j];
            }
        }
    }
}

}  // namespace

extern "C" void kernel_launch(void* const* d_in, const int* in_sizes, int n_in,
                              void* d_out, int out_size) {
    (void)in_sizes; (void)n_in; (void)out_size;
    const float2* xy  = (const float2*)d_in[0];
    const float2* tab = (const float2*)d_in[1];
    const float*  W0  = (const float*)d_in[2];
    const float*  W1  = (const float*)d_in[3];
    const float*  W2  = (const float*)d_in[4];
    float* out = (float*)d_out;

    ngp_mma_kernel<<<GRID, THREADS>>>(xy, tab, W0, W1, W2, out);
}

// round 15
// speedup vs baseline: 1.2247x; 1.2247x over previous
#include <cuda_runtime.h>
#include <cstdint>

// InstantNGP: hash-grid encode + MLP 32->64->64->3, all three layers as
// warp-level fp16 mma.sync m16n8k16 (f32 accumulate).
// Round-15 = R12 base (TPW=8, GRID=2048) with:
//  - W2 epilogue as a 4-MMA pass (B = 64x8 zero-padded W2), fragment
//    passthrough from layer-1 C frags; direct predicated STG from C2.
//  - layer-0 B frags [nt][lane] uint4 (one LDS.128/nt);
//    layer-1 B frags [kkp][nt][lane] uint4 (16 LDS.128 instead of 32 LDS.64).
//  - enc 2^8 scaling undone by one exact f32 multiply on outputs.

namespace {

constexpr int S_DIM   = 1024;
constexpr int NPTS    = S_DIM * S_DIM;
constexpr int TBL     = 1 << 19;

constexpr int WARPS   = 4;
constexpr int THREADS = WARPS * 32;
constexpr int TILE    = 16;               // points per warp-tile
constexpr int TPW     = 8;                // tiles per warp
constexpr int PPW     = TILE * TPW;       // 128 points per warp
constexpr int GRID    = NPTS / (PPW * WARPS);   // 2048
constexpr int ESTRIDE = 20;               // uint32 per enc row (swizzled, conflict-free)
constexpr float ESCALE   = 256.0f;        // 2^8: lift enc out of fp16 subnormal range
constexpr float ESCALE_I = 1.0f / 256.0f;

__device__ __forceinline__ uint32_t f16x2(float lo, float hi) {
    uint32_t r;
    asm("cvt.rn.f16x2.f32 %0, %1, %2;" : "=r"(r) : "f"(hi), "f"(lo));
    return r;
}

__device__ __forceinline__ int eidx(int row, int col) {
    return row * ESTRIDE + (col ^ ((row >> 3) << 1));
}

__device__ __forceinline__ void mma16(float* d,
                                      uint32_t a0, uint32_t a1, uint32_t a2, uint32_t a3,
                                      uint32_t b0, uint32_t b1) {
    asm volatile(
        "mma.sync.aligned.m16n8k16.row.col.f32.f16.f16.f32 "
        "{%0,%1,%2,%3},{%4,%5,%6,%7},{%8,%9},{%0,%1,%2,%3};"
        : "+f"(d[0]), "+f"(d[1]), "+f"(d[2]), "+f"(d[3])
        : "r"(a0), "r"(a1), "r"(a2), "r"(a3), "r"(b0), "r"(b1));
}

__global__ __launch_bounds__(THREADS, 5) void ngp_mma_kernel(
    const float2* __restrict__ xy,
    const float2* __restrict__ tab,
    const float*  __restrict__ W0,     // (32, 64) [k][n]
    const float*  __restrict__ W1,     // (64, 64) [k][n]
    const float*  __restrict__ W2,     // (64, 3)  [k][j]
    float*        __restrict__ out)    // (3, S, S)
{
    __shared__ uint4    w0q[8][32];          // 4 KB  B frags layer0: [nt][lane] = kk0|kk1
    __shared__ uint4    w1q[2][8][32];       // 8 KB  B frags layer1: [kkp][nt][lane]
    __shared__ uint2    w2f[4][32];          // 1 KB  B frags W2 (8 cols, 0..2 real)
    __shared__ uint32_t scratch[WARPS][TILE * ESTRIDE];  // 5 KB enc (fp16x2)

    const int tid = threadIdx.x;

    // ---- stage weights in fragment order (once per CTA) ----
    for (int i = tid; i < 8 * 32; i += THREADS) {
        const int nt = i >> 5, ln = i & 31;
        const int t = ln & 3, gg = ln >> 2, n = nt * 8 + gg;
        uint32_t v[4];
#pragma unroll
        for (int kk = 0; kk < 2; kk++) {
            const int kb = 16 * kk + 2 * t;
            v[2 * kk]     = f16x2(W0[kb * 64 + n],       W0[(kb + 1) * 64 + n]);
            v[2 * kk + 1] = f16x2(W0[(kb + 8) * 64 + n], W0[(kb + 9) * 64 + n]);
        }
        w0q[nt][ln] = make_uint4(v[0], v[1], v[2], v[3]);
    }
    for (int i = tid; i < 2 * 8 * 32; i += THREADS) {
        const int kkp = i >> 8, nt = (i >> 5) & 7, ln = i & 31;
        const int t = ln & 3, gg = ln >> 2, n = nt * 8 + gg;
        uint32_t v[4];
#pragma unroll
        for (int s = 0; s < 2; s++) {
            const int kb = 16 * (2 * kkp + s) + 2 * t;
            v[2 * s]     = f16x2(W1[kb * 64 + n],       W1[(kb + 1) * 64 + n]);
            v[2 * s + 1] = f16x2(W1[(kb + 8) * 64 + n], W1[(kb + 9) * 64 + n]);
        }
        w1q[kkp][nt][ln] = make_uint4(v[0], v[1], v[2], v[3]);
    }
    for (int i = tid; i < 4 * 32; i += THREADS) {
        const int kk = i >> 5, ln = i & 31;
        const int t = ln & 3, gg = ln >> 2;
        const int kb = 16 * kk + 2 * t;
        float lo0 = 0.f, hi0 = 0.f, lo1 = 0.f, hi1 = 0.f;
        if (gg < 3) {
            lo0 = W2[kb * 3 + gg];       hi0 = W2[(kb + 1) * 3 + gg];
            lo1 = W2[(kb + 8) * 3 + gg]; hi1 = W2[(kb + 9) * 3 + gg];
        }
        w2f[kk][ln] = make_uint2(f16x2(lo0, hi0), f16x2(lo1, hi1));
    }
    __syncthreads();

    const int wid  = tid >> 5;
    const int lane = tid & 31;
    const int t    = lane & 3;          // threadIDInGroup
    const int g    = lane >> 2;         // groupID (row within 8)
    const int h    = lane >> 4;         // level parity for encode
    const int pl   = lane & 15;         // point within tile for encode
    uint32_t* buf  = scratch[wid];
    const int wg   = blockIdx.x * WARPS + wid;

    // floor(16 * 1.5^l): even levels / odd levels
    const int res_e[8] = {16, 36, 81, 182, 410, 922, 2075, 4670};
    const int res_o[8] = {24, 54, 121, 273, 615, 1383, 3113, 7006};

    for (int tile = 0; tile < TPW; tile++) {
        const int tb = wg * PPW + tile * TILE;
        __syncwarp();

        // ---- encode: point pl, levels 2*lp + h; store fp16x2 (f0,f1)*2^8 ----
        const float2 p = __ldg(&xy[tb + pl]);
        const float c0 = p.x, c1 = p.y;
#pragma unroll
        for (int lp = 0; lp < 8; lp++) {
            const int res   = h ? res_o[lp] : res_e[lp];
            const int level = 2 * lp + h;
            const bool dense = (lp < 5);   // levels 0..9 dense, 10..15 hashed

            const float fres = (float)res;
            const float px = c0 * fres;
            const float py = c1 * fres;
            const float fx = floorf(px);
            const float fy = floorf(py);
            const float wx = px - fx;
            const float wy = py - fy;
            const int ix = (int)fx;
            const int iy = (int)fy;

            int i00, i01, i10, i11;
            if (dense) {
                const int r1 = res + 1;
                i00 = ix + iy * r1;
                i01 = i00 + r1;
                i10 = i00 + 1;
                i11 = i01 + 1;
            } else {
                const uint32_t P = 2654435761u;
                const uint32_t ux = (uint32_t)ix;
                const uint32_t uy = (uint32_t)iy;
                const uint32_t hy0 = uy * P;
                const uint32_t hy1 = (uy + 1u) * P;
                i00 = (int)((ux        ^ hy0) & (uint32_t)(TBL - 1));
                i01 = (int)((ux        ^ hy1) & (uint32_t)(TBL - 1));
                i10 = (int)(((ux + 1u) ^ hy0) & (uint32_t)(TBL - 1));
                i11 = (int)(((ux + 1u) ^ hy1) & (uint32_t)(TBL - 1));
            }

            const float2* lt = tab + (size_t)level * TBL;
            const float2 a00 = __ldg(lt + i00);
            const float2 a01 = __ldg(lt + i01);
            const float2 a10 = __ldg(lt + i10);
            const float2 a11 = __ldg(lt + i11);

            const float w00 = (1.0f - wx) * (1.0f - wy);
            const float w01 = (1.0f - wx) * wy;
            const float w10 = wx * (1.0f - wy);
            const float w11 = wx * wy;

            const float f0 = a00.x * w00 + a01.x * w01 + a10.x * w10 + a11.x * w11;
            const float f1 = a00.y * w00 + a01.y * w01 + a10.y * w10 + a11.y * w11;

            buf[eidx(pl, level)] = f16x2(f0 * ESCALE, f1 * ESCALE);
        }
        __syncwarp();

        // ---- layer 0: (16x32) @ (32x64), m16n8k16, one LDS.128 per nt ----
        float C[8][4];
#pragma unroll
        for (int nt = 0; nt < 8; nt++)
#pragma unroll
            for (int j = 0; j < 4; j++) C[nt][j] = 0.0f;

        {
            const uint32_t a0k0 = buf[eidx(g,     t)];
            const uint32_t a1k0 = buf[eidx(g + 8, t)];
            const uint32_t a2k0 = buf[eidx(g,     t + 4)];
            const uint32_t a3k0 = buf[eidx(g + 8, t + 4)];
            const uint32_t a0k1 = buf[eidx(g,     8 + t)];
            const uint32_t a1k1 = buf[eidx(g + 8, 8 + t)];
            const uint32_t a2k1 = buf[eidx(g,     8 + t + 4)];
            const uint32_t a3k1 = buf[eidx(g + 8, 8 + t + 4)];
#pragma unroll
            for (int nt = 0; nt < 8; nt++) {
                const uint4 b = w0q[nt][lane];
                mma16(C[nt], a0k0, a1k0, a2k0, a3k0, b.x, b.y);
                mma16(C[nt], a0k1, a1k1, a2k1, a3k1, b.z, b.w);
            }
        }

        // ---- pack layer-1 A fragments (C dies here) ----
        uint32_t A[4][4];
#pragma unroll
        for (int kk = 0; kk < 4; kk++) {
            A[kk][0] = f16x2(fmaxf(C[2 * kk][0], 0.0f),     fmaxf(C[2 * kk][1], 0.0f));
            A[kk][1] = f16x2(fmaxf(C[2 * kk][2], 0.0f),     fmaxf(C[2 * kk][3], 0.0f));
            A[kk][2] = f16x2(fmaxf(C[2 * kk + 1][0], 0.0f), fmaxf(C[2 * kk + 1][1], 0.0f));
            A[kk][3] = f16x2(fmaxf(C[2 * kk + 1][2], 0.0f), fmaxf(C[2 * kk + 1][3], 0.0f));
        }

        // ---- layer 1 + W2 as MMA: per kk2 build h1 A-frag, feed C2 ----
        float C2[4] = {0.f, 0.f, 0.f, 0.f};
#pragma unroll
        for (int kk2 = 0; kk2 < 4; kk2++) {
            uint32_t A2[4];
#pragma unroll
            for (int s = 0; s < 2; s++) {
                const int nt = 2 * kk2 + s;
                float C1[4] = {0.f, 0.f, 0.f, 0.f};
#pragma unroll
                for (int kkp = 0; kkp < 2; kkp++) {
                    const uint4 b = w1q[kkp][nt][lane];
                    mma16(C1, A[2 * kkp][0],     A[2 * kkp][1],     A[2 * kkp][2],     A[2 * kkp][3],     b.x, b.y);
                    mma16(C1, A[2 * kkp + 1][0], A[2 * kkp + 1][1], A[2 * kkp + 1][2], A[2 * kkp + 1][3], b.z, b.w);
                }
                A2[2 * s]     = f16x2(fmaxf(C1[0], 0.0f), fmaxf(C1[1], 0.0f));
                A2[2 * s + 1] = f16x2(fmaxf(C1[2], 0.0f), fmaxf(C1[3], 0.0f));
            }
            const uint2 b2 = w2f[kk2][lane];
            mma16(C2, A2[0], A2[1], A2[2], A2[3], b2.x, b2.y);
        }

        // ---- direct store from C2 fragment (cols: t=0 -> j0,j1; t=1 -> j2) ----
        if (t == 0) {
            out[0 * NPTS + tb + g]     = C2[0] * ESCALE_I;
            out[1 * NPTS + tb + g]     = C2[1] * ESCALE_I;
            out[0 * NPTS + tb + g + 8] = C2[2] * ESCALE_I;
            out[1 * NPTS + tb + g + 8] = C2[3] * ESCALE_I;
        } else if (t == 1) {
            out[2 * NPTS + tb + g]     = C2[0] * ESCALE_I;
            out[2 * NPTS + tb + g + 8] = C2[2] * ESCALE_I;
        }
    }
}

}  // namespace

extern "C" void kernel_launch(void* const* d_in, const int* in_sizes, int n_in,
                              void* d_out, int out_size) {
    (void)in_sizes; (void)n_in; (void)out_size;
    const float2* xy  = (const float2*)d_in[0];
    const float2* tab = (const float2*)d_in[1];
    const float*  W0  = (const float*)d_in[2];
    const float*  W1  = (const float*)d_in[3];
    const float*  W2  = (const float*)d_in[4];
    float* out = (float*)d_out;

    ngp_mma_kernel<<<GRID, THREADS>>>(xy, tab, W0, W1, W2, out);
}

// round 16
// speedup vs baseline: 1.2594x; 1.0284x over previous
#include <cuda_runtime.h>
#include <cstdint>

// InstantNGP: hash-grid encode + MLP 32->64->64->3, all three layers as
// warp-level fp16 mma.sync m16n8k16 (f32 accumulate).
// Round-16 = R15 with:
//  - double-buffered pipeline: encode(t+1) issued before consume(t), one
//    syncwarp per iteration -> gather latency overlaps MMA/pack/store.
//  - factored bilinear (3 lerps) + hy1 = hy0 + P  (fewer encode instr).

namespace {

constexpr int S_DIM   = 1024;
constexpr int NPTS    = S_DIM * S_DIM;
constexpr int TBL     = 1 << 19;

constexpr int WARPS   = 4;
constexpr int THREADS = WARPS * 32;
constexpr int TILE    = 16;               // points per warp-tile
constexpr int TPW     = 8;                // tiles per warp
constexpr int PPW     = TILE * TPW;       // 128 points per warp
constexpr int GRID    = NPTS / (PPW * WARPS);   // 2048
constexpr int ESTRIDE = 20;               // uint32 per enc row (swizzled, conflict-free)
constexpr float ESCALE   = 256.0f;        // 2^8: lift enc out of fp16 subnormal range
constexpr float ESCALE_I = 1.0f / 256.0f;

__device__ __forceinline__ uint32_t f16x2(float lo, float hi) {
    uint32_t r;
    asm("cvt.rn.f16x2.f32 %0, %1, %2;" : "=r"(r) : "f"(hi), "f"(lo));
    return r;
}

__device__ __forceinline__ int eidx(int row, int col) {
    return row * ESTRIDE + (col ^ ((row >> 3) << 1));
}

__device__ __forceinline__ void mma16(float* d,
                                      uint32_t a0, uint32_t a1, uint32_t a2, uint32_t a3,
                                      uint32_t b0, uint32_t b1) {
    asm volatile(
        "mma.sync.aligned.m16n8k16.row.col.f32.f16.f16.f32 "
        "{%0,%1,%2,%3},{%4,%5,%6,%7},{%8,%9},{%0,%1,%2,%3};"
        : "+f"(d[0]), "+f"(d[1]), "+f"(d[2]), "+f"(d[3])
        : "r"(a0), "r"(a1), "r"(a2), "r"(a3), "r"(b0), "r"(b1));
}

__global__ __launch_bounds__(THREADS, 4) void ngp_mma_kernel(
    const float2* __restrict__ xy,
    const float2* __restrict__ tab,
    const float*  __restrict__ W0,     // (32, 64) [k][n]
    const float*  __restrict__ W1,     // (64, 64) [k][n]
    const float*  __restrict__ W2,     // (64, 3)  [k][j]
    float*        __restrict__ out)    // (3, S, S)
{
    __shared__ uint4    w0q[8][32];          // 4 KB  B frags layer0: [nt][lane] = kk0|kk1
    __shared__ uint4    w1q[2][8][32];       // 8 KB  B frags layer1: [kkp][nt][lane]
    __shared__ uint2    w2f[4][32];          // 1 KB  B frags W2 (8 cols, 0..2 real)
    __shared__ uint32_t scratch[WARPS][2][TILE * ESTRIDE];  // 10 KB enc, double-buffered

    const int tid = threadIdx.x;

    // ---- stage weights in fragment order (once per CTA) ----
    for (int i = tid; i < 8 * 32; i += THREADS) {
        const int nt = i >> 5, ln = i & 31;
        const int t = ln & 3, gg = ln >> 2, n = nt * 8 + gg;
        uint32_t v[4];
#pragma unroll
        for (int kk = 0; kk < 2; kk++) {
            const int kb = 16 * kk + 2 * t;
            v[2 * kk]     = f16x2(W0[kb * 64 + n],       W0[(kb + 1) * 64 + n]);
            v[2 * kk + 1] = f16x2(W0[(kb + 8) * 64 + n], W0[(kb + 9) * 64 + n]);
        }
        w0q[nt][ln] = make_uint4(v[0], v[1], v[2], v[3]);
    }
    for (int i = tid; i < 2 * 8 * 32; i += THREADS) {
        const int kkp = i >> 8, nt = (i >> 5) & 7, ln = i & 31;
        const int t = ln & 3, gg = ln >> 2, n = nt * 8 + gg;
        uint32_t v[4];
#pragma unroll
        for (int s = 0; s < 2; s++) {
            const int kb = 16 * (2 * kkp + s) + 2 * t;
            v[2 * s]     = f16x2(W1[kb * 64 + n],       W1[(kb + 1) * 64 + n]);
            v[2 * s + 1] = f16x2(W1[(kb + 8) * 64 + n], W1[(kb + 9) * 64 + n]);
        }
        w1q[kkp][nt][ln] = make_uint4(v[0], v[1], v[2], v[3]);
    }
    for (int i = tid; i < 4 * 32; i += THREADS) {
        const int kk = i >> 5, ln = i & 31;
        const int t = ln & 3, gg = ln >> 2;
        const int kb = 16 * kk + 2 * t;
        float lo0 = 0.f, hi0 = 0.f, lo1 = 0.f, hi1 = 0.f;
        if (gg < 3) {
            lo0 = W2[kb * 3 + gg];       hi0 = W2[(kb + 1) * 3 + gg];
            lo1 = W2[(kb + 8) * 3 + gg]; hi1 = W2[(kb + 9) * 3 + gg];
        }
        w2f[kk][ln] = make_uint2(f16x2(lo0, hi0), f16x2(lo1, hi1));
    }
    __syncthreads();

    const int wid  = tid >> 5;
    const int lane = tid & 31;
    const int t    = lane & 3;          // threadIDInGroup
    const int g    = lane >> 2;         // groupID (row within 8)
    const int h    = lane >> 4;         // level parity for encode
    const int pl   = lane & 15;         // point within tile for encode
    const int wg   = blockIdx.x * WARPS + wid;

    // floor(16 * 1.5^l): even levels / odd levels
    const int res_e[8] = {16, 36, 81, 182, 410, 922, 2075, 4670};
    const int res_o[8] = {24, 54, 121, 273, 615, 1383, 3113, 7006};

    // ---- encode one tile into dst (this thread: point pl, parity-h levels) ----
    auto encode_tile = [&](int tileIdx, uint32_t* dst) {
        const int tb = wg * PPW + tileIdx * TILE;
        const float2 p = __ldg(&xy[tb + pl]);
        const float c0 = p.x, c1 = p.y;
#pragma unroll
        for (int lp = 0; lp < 8; lp++) {
            const int res   = h ? res_o[lp] : res_e[lp];
            const int level = 2 * lp + h;
            const bool dense = (lp < 5);   // levels 0..9 dense, 10..15 hashed

            const float fres = (float)res;
            const float px = c0 * fres;
            const float py = c1 * fres;
            const float fx = floorf(px);
            const float fy = floorf(py);
            const float wx = px - fx;
            const float wy = py - fy;
            const int ix = (int)fx;
            const int iy = (int)fy;

            int i00, i01, i10, i11;
            if (dense) {
                const int r1 = res + 1;
                i00 = ix + iy * r1;
                i01 = i00 + r1;
                i10 = i00 + 1;
                i11 = i01 + 1;
            } else {
                const uint32_t P = 2654435761u;
                const uint32_t ux = (uint32_t)ix;
                const uint32_t uy = (uint32_t)iy;
                const uint32_t hy0 = uy * P;
                const uint32_t hy1 = hy0 + P;        // (uy+1)*P, exact mod 2^32
                i00 = (int)((ux        ^ hy0) & (uint32_t)(TBL - 1));
                i01 = (int)((ux        ^ hy1) & (uint32_t)(TBL - 1));
                i10 = (int)(((ux + 1u) ^ hy0) & (uint32_t)(TBL - 1));
                i11 = (int)(((ux + 1u) ^ hy1) & (uint32_t)(TBL - 1));
            }

            const float2* lt = tab + (size_t)level * TBL;
            const float2 a00 = __ldg(lt + i00);
            const float2 a01 = __ldg(lt + i01);
            const float2 a10 = __ldg(lt + i10);
            const float2 a11 = __ldg(lt + i11);

            // factored bilinear: x-lerps then y-lerp (12 ops for both feats)
            const float gx0x = fmaf(wx, a10.x - a00.x, a00.x);
            const float gx0y = fmaf(wx, a10.y - a00.y, a00.y);
            const float gx1x = fmaf(wx, a11.x - a01.x, a01.x);
            const float gx1y = fmaf(wx, a11.y - a01.y, a01.y);
            const float f0 = fmaf(wy, gx1x - gx0x, gx0x);
            const float f1 = fmaf(wy, gx1y - gx0y, gx0y);

            dst[eidx(pl, level)] = f16x2(f0 * ESCALE, f1 * ESCALE);
        }
    };

    encode_tile(0, scratch[wid][0]);
    __syncwarp();

    for (int tile = 0; tile < TPW; tile++) {
        uint32_t* buf = scratch[wid][tile & 1];

        // ---- pipeline: issue next tile's gathers before consuming this one ----
        if (tile + 1 < TPW)
            encode_tile(tile + 1, scratch[wid][(tile + 1) & 1]);

        // ---- layer 0: (16x32) @ (32x64), m16n8k16, one LDS.128 per nt ----
        float C[8][4];
#pragma unroll
        for (int nt = 0; nt < 8; nt++)
#pragma unroll
            for (int j = 0; j < 4; j++) C[nt][j] = 0.0f;

        {
            const uint32_t a0k0 = buf[eidx(g,     t)];
            const uint32_t a1k0 = buf[eidx(g + 8, t)];
            const uint32_t a2k0 = buf[eidx(g,     t + 4)];
            const uint32_t a3k0 = buf[eidx(g + 8, t + 4)];
            const uint32_t a0k1 = buf[eidx(g,     8 + t)];
            const uint32_t a1k1 = buf[eidx(g + 8, 8 + t)];
            const uint32_t a2k1 = buf[eidx(g,     8 + t + 4)];
            const uint32_t a3k1 = buf[eidx(g + 8, 8 + t + 4)];
#pragma unroll
            for (int nt = 0; nt < 8; nt++) {
                const uint4 b = w0q[nt][lane];
                mma16(C[nt], a0k0, a1k0, a2k0, a3k0, b.x, b.y);
                mma16(C[nt], a0k1, a1k1, a2k1, a3k1, b.z, b.w);
            }
        }

        // ---- pack layer-1 A fragments (C dies here) ----
        uint32_t A[4][4];
#pragma unroll
        for (int kk = 0; kk < 4; kk++) {
            A[kk][0] = f16x2(fmaxf(C[2 * kk][0], 0.0f),     fmaxf(C[2 * kk][1], 0.0f));
            A[kk][1] = f16x2(fmaxf(C[2 * kk][2], 0.0f),     fmaxf(C[2 * kk][3], 0.0f));
            A[kk][2] = f16x2(fmaxf(C[2 * kk + 1][0], 0.0f), fmaxf(C[2 * kk + 1][1], 0.0f));
            A[kk][3] = f16x2(fmaxf(C[2 * kk + 1][2], 0.0f), fmaxf(C[2 * kk + 1][3], 0.0f));
        }

        // ---- layer 1 + W2 as MMA: per kk2 build h1 A-frag, feed C2 ----
        float C2[4] = {0.f, 0.f, 0.f, 0.f};
#pragma unroll
        for (int kk2 = 0; kk2 < 4; kk2++) {
            uint32_t A2[4];
#pragma unroll
            for (int s = 0; s < 2; s++) {
                const int nt = 2 * kk2 + s;
                float C1[4] = {0.f, 0.f, 0.f, 0.f};
#pragma unroll
                for (int kkp = 0; kkp < 2; kkp++) {
                    const uint4 b = w1q[kkp][nt][lane];
                    mma16(C1, A[2 * kkp][0],     A[2 * kkp][1],     A[2 * kkp][2],     A[2 * kkp][3],     b.x, b.y);
                    mma16(C1, A[2 * kkp + 1][0], A[2 * kkp + 1][1], A[2 * kkp + 1][2], A[2 * kkp + 1][3], b.z, b.w);
                }
                A2[2 * s]     = f16x2(fmaxf(C1[0], 0.0f), fmaxf(C1[1], 0.0f));
                A2[2 * s + 1] = f16x2(fmaxf(C1[2], 0.0f), fmaxf(C1[3], 0.0f));
            }
            const uint2 b2 = w2f[kk2][lane];
            mma16(C2, A2[0], A2[1], A2[2], A2[3], b2.x, b2.y);
        }

        // ---- direct store from C2 fragment (cols: t=0 -> j0,j1; t=1 -> j2) ----
        const int tb = wg * PPW + tile * TILE;
        if (t == 0) {
            out[0 * NPTS + tb + g]     = C2[0] * ESCALE_I;
            out[1 * NPTS + tb + g]     = C2[1] * ESCALE_I;
            out[0 * NPTS + tb + g + 8] = C2[2] * ESCALE_I;
            out[1 * NPTS + tb + g + 8] = C2[3] * ESCALE_I;
        } else if (t == 1) {
            out[2 * NPTS + tb + g]     = C2[0] * ESCALE_I;
            out[2 * NPTS + tb + g + 8] = C2[2] * ESCALE_I;
        }

        __syncwarp();   // next tile's buffer writes complete before its reads
    }
}

}  // namespace

extern "C" void kernel_launch(void* const* d_in, const int* in_sizes, int n_in,
                              void* d_out, int out_size) {
    (void)in_sizes; (void)n_in; (void)out_size;
    const float2* xy  = (const float2*)d_in[0];
    const float2* tab = (const float2*)d_in[1];
    const float*  W0  = (const float*)d_in[2];
    const float*  W1  = (const float*)d_in[3];
    const float*  W2  = (const float*)d_in[4];
    float* out = (float*)d_out;

    ngp_mma_kernel<<<GRID, THREADS>>>(xy, tab, W0, W1, W2, out);
}

// round 17
// speedup vs baseline: 1.2662x; 1.0053x over previous
#include <cuda_runtime.h>
#include <cstdint>

// InstantNGP: hash-grid encode + MLP 32->64->64->3, all three layers as
// warp-level fp16 mma.sync m16n8k16 (f32 accumulate).
// Round-17 = R15/R16 with M=32 B-sharing: two 16-point tiles per iteration
// share every B-fragment load (w0q/w1q/w2f LDS halved -> ~24% less L1 work).
// Layer-0 C doubles (64 regs) but layer1+W2 stay nt-outer/ephemeral.
// Encode pipelining dropped (reg budget goes to the two C sets).

namespace {

constexpr int S_DIM   = 1024;
constexpr int NPTS    = S_DIM * S_DIM;
constexpr int TBL     = 1 << 19;

constexpr int WARPS   = 4;
constexpr int THREADS = WARPS * 32;
constexpr int TILE    = 16;               // points per MMA tile
constexpr int PAIRS   = 4;                // tile-pairs per warp
constexpr int PPW     = TILE * 2 * PAIRS; // 128 points per warp
constexpr int GRID    = NPTS / (PPW * WARPS);   // 2048
constexpr int ESTRIDE = 20;               // uint32 per enc row (swizzled, conflict-free)
constexpr float ESCALE   = 256.0f;        // 2^8: lift enc out of fp16 subnormal range
constexpr float ESCALE_I = 1.0f / 256.0f;

__device__ __forceinline__ uint32_t f16x2(float lo, float hi) {
    uint32_t r;
    asm("cvt.rn.f16x2.f32 %0, %1, %2;" : "=r"(r) : "f"(hi), "f"(lo));
    return r;
}

__device__ __forceinline__ int eidx(int row, int col) {
    return row * ESTRIDE + (col ^ ((row >> 3) << 1));
}

__device__ __forceinline__ void mma16(float* d,
                                      uint32_t a0, uint32_t a1, uint32_t a2, uint32_t a3,
                                      uint32_t b0, uint32_t b1) {
    asm volatile(
        "mma.sync.aligned.m16n8k16.row.col.f32.f16.f16.f32 "
        "{%0,%1,%2,%3},{%4,%5,%6,%7},{%8,%9},{%0,%1,%2,%3};"
        : "+f"(d[0]), "+f"(d[1]), "+f"(d[2]), "+f"(d[3])
        : "r"(a0), "r"(a1), "r"(a2), "r"(a3), "r"(b0), "r"(b1));
}

__global__ __launch_bounds__(THREADS, 4) void ngp_mma_kernel(
    const float2* __restrict__ xy,
    const float2* __restrict__ tab,
    const float*  __restrict__ W0,     // (32, 64) [k][n]
    const float*  __restrict__ W1,     // (64, 64) [k][n]
    const float*  __restrict__ W2,     // (64, 3)  [k][j]
    float*        __restrict__ out)    // (3, S, S)
{
    __shared__ uint4    w0q[8][32];          // 4 KB  B frags layer0: [nt][lane] = kk0|kk1
    __shared__ uint4    w1q[2][8][32];       // 8 KB  B frags layer1: [kkp][nt][lane]
    __shared__ uint2    w2f[4][32];          // 1 KB  B frags W2 (8 cols, 0..2 real)
    __shared__ uint32_t scratch[WARPS][2][TILE * ESTRIDE];  // 10 KB enc (2 tiles/warp)

    const int tid = threadIdx.x;

    // ---- stage weights in fragment order (once per CTA) ----
    for (int i = tid; i < 8 * 32; i += THREADS) {
        const int nt = i >> 5, ln = i & 31;
        const int t = ln & 3, gg = ln >> 2, n = nt * 8 + gg;
        uint32_t v[4];
#pragma unroll
        for (int kk = 0; kk < 2; kk++) {
            const int kb = 16 * kk + 2 * t;
            v[2 * kk]     = f16x2(W0[kb * 64 + n],       W0[(kb + 1) * 64 + n]);
            v[2 * kk + 1] = f16x2(W0[(kb + 8) * 64 + n], W0[(kb + 9) * 64 + n]);
        }
        w0q[nt][ln] = make_uint4(v[0], v[1], v[2], v[3]);
    }
    for (int i = tid; i < 2 * 8 * 32; i += THREADS) {
        const int kkp = i >> 8, nt = (i >> 5) & 7, ln = i & 31;
        const int t = ln & 3, gg = ln >> 2, n = nt * 8 + gg;
        uint32_t v[4];
#pragma unroll
        for (int s = 0; s < 2; s++) {
            const int kb = 16 * (2 * kkp + s) + 2 * t;
            v[2 * s]     = f16x2(W1[kb * 64 + n],       W1[(kb + 1) * 64 + n]);
            v[2 * s + 1] = f16x2(W1[(kb + 8) * 64 + n], W1[(kb + 9) * 64 + n]);
        }
        w1q[kkp][nt][ln] = make_uint4(v[0], v[1], v[2], v[3]);
    }
    for (int i = tid; i < 4 * 32; i += THREADS) {
        const int kk = i >> 5, ln = i & 31;
        const int t = ln & 3, gg = ln >> 2;
        const int kb = 16 * kk + 2 * t;
        float lo0 = 0.f, hi0 = 0.f, lo1 = 0.f, hi1 = 0.f;
        if (gg < 3) {
            lo0 = W2[kb * 3 + gg];       hi0 = W2[(kb + 1) * 3 + gg];
            lo1 = W2[(kb + 8) * 3 + gg]; hi1 = W2[(kb + 9) * 3 + gg];
        }
        w2f[kk][ln] = make_uint2(f16x2(lo0, hi0), f16x2(lo1, hi1));
    }
    __syncthreads();

    const int wid  = tid >> 5;
    const int lane = tid & 31;
    const int t    = lane & 3;          // threadIDInGroup
    const int g    = lane >> 2;         // groupID (row within 8)
    const int h    = lane >> 4;         // level parity for encode
    const int pl   = lane & 15;         // point within tile for encode
    const int wg   = blockIdx.x * WARPS + wid;

    // floor(16 * 1.5^l): even levels / odd levels
    const int res_e[8] = {16, 36, 81, 182, 410, 922, 2075, 4670};
    const int res_o[8] = {24, 54, 121, 273, 615, 1383, 3113, 7006};

    // ---- encode one tile into dst (this thread: point pl, parity-h levels) ----
    auto encode_tile = [&](int tileIdx, uint32_t* dst) {
        const int tb = wg * PPW + tileIdx * TILE;
        const float2 p = __ldg(&xy[tb + pl]);
        const float c0 = p.x, c1 = p.y;
#pragma unroll
        for (int lp = 0; lp < 8; lp++) {
            const int res   = h ? res_o[lp] : res_e[lp];
            const int level = 2 * lp + h;
            const bool dense = (lp < 5);   // levels 0..9 dense, 10..15 hashed

            const float fres = (float)res;
            const float px = c0 * fres;
            const float py = c1 * fres;
            const float fx = floorf(px);
            const float fy = floorf(py);
            const float wx = px - fx;
            const float wy = py - fy;
            const int ix = (int)fx;
            const int iy = (int)fy;

            int i00, i01, i10, i11;
            if (dense) {
                const int r1 = res + 1;
                i00 = ix + iy * r1;
                i01 = i00 + r1;
                i10 = i00 + 1;
                i11 = i01 + 1;
            } else {
                const uint32_t P = 2654435761u;
                const uint32_t ux = (uint32_t)ix;
                const uint32_t uy = (uint32_t)iy;
                const uint32_t hy0 = uy * P;
                const uint32_t hy1 = hy0 + P;        // (uy+1)*P, exact mod 2^32
                i00 = (int)((ux        ^ hy0) & (uint32_t)(TBL - 1));
                i01 = (int)((ux        ^ hy1) & (uint32_t)(TBL - 1));
                i10 = (int)(((ux + 1u) ^ hy0) & (uint32_t)(TBL - 1));
                i11 = (int)(((ux + 1u) ^ hy1) & (uint32_t)(TBL - 1));
            }

            const float2* lt = tab + (size_t)level * TBL;
            const float2 a00 = __ldg(lt + i00);
            const float2 a01 = __ldg(lt + i01);
            const float2 a10 = __ldg(lt + i10);
            const float2 a11 = __ldg(lt + i11);

            // factored bilinear: x-lerps then y-lerp
            const float gx0x = fmaf(wx, a10.x - a00.x, a00.x);
            const float gx0y = fmaf(wx, a10.y - a00.y, a00.y);
            const float gx1x = fmaf(wx, a11.x - a01.x, a01.x);
            const float gx1y = fmaf(wx, a11.y - a01.y, a01.y);
            const float f0 = fmaf(wy, gx1x - gx0x, gx0x);
            const float f1 = fmaf(wy, gx1y - gx0y, gx0y);

            dst[eidx(pl, level)] = f16x2(f0 * ESCALE, f1 * ESCALE);
        }
    };

    for (int pr = 0; pr < PAIRS; pr++) {
        uint32_t* buf0 = scratch[wid][0];
        uint32_t* buf1 = scratch[wid][1];

        encode_tile(2 * pr,     buf0);
        encode_tile(2 * pr + 1, buf1);
        __syncwarp();

        // ---- layer 0: both tiles share each w0q fragment ----
        float Ca[8][4], Cb[8][4];
#pragma unroll
        for (int nt = 0; nt < 8; nt++)
#pragma unroll
            for (int j = 0; j < 4; j++) { Ca[nt][j] = 0.0f; Cb[nt][j] = 0.0f; }

        {
            const uint32_t a0k0a = buf0[eidx(g,     t)];
            const uint32_t a1k0a = buf0[eidx(g + 8, t)];
            const uint32_t a2k0a = buf0[eidx(g,     t + 4)];
            const uint32_t a3k0a = buf0[eidx(g + 8, t + 4)];
            const uint32_t a0k1a = buf0[eidx(g,     8 + t)];
            const uint32_t a1k1a = buf0[eidx(g + 8, 8 + t)];
            const uint32_t a2k1a = buf0[eidx(g,     8 + t + 4)];
            const uint32_t a3k1a = buf0[eidx(g + 8, 8 + t + 4)];
            const uint32_t a0k0b = buf1[eidx(g,     t)];
            const uint32_t a1k0b = buf1[eidx(g + 8, t)];
            const uint32_t a2k0b = buf1[eidx(g,     t + 4)];
            const uint32_t a3k0b = buf1[eidx(g + 8, t + 4)];
            const uint32_t a0k1b = buf1[eidx(g,     8 + t)];
            const uint32_t a1k1b = buf1[eidx(g + 8, 8 + t)];
            const uint32_t a2k1b = buf1[eidx(g,     8 + t + 4)];
            const uint32_t a3k1b = buf1[eidx(g + 8, 8 + t + 4)];
#pragma unroll
            for (int nt = 0; nt < 8; nt++) {
                const uint4 b = w0q[nt][lane];
                mma16(Ca[nt], a0k0a, a1k0a, a2k0a, a3k0a, b.x, b.y);
                mma16(Ca[nt], a0k1a, a1k1a, a2k1a, a3k1a, b.z, b.w);
                mma16(Cb[nt], a0k0b, a1k0b, a2k0b, a3k0b, b.x, b.y);
                mma16(Cb[nt], a0k1b, a1k1b, a2k1b, a3k1b, b.z, b.w);
            }
        }

        // ---- pack layer-1 A fragments for both tiles (C dies here) ----
        uint32_t Aa[4][4], Ab[4][4];
#pragma unroll
        for (int kk = 0; kk < 4; kk++) {
            Aa[kk][0] = f16x2(fmaxf(Ca[2 * kk][0], 0.0f),     fmaxf(Ca[2 * kk][1], 0.0f));
            Aa[kk][1] = f16x2(fmaxf(Ca[2 * kk][2], 0.0f),     fmaxf(Ca[2 * kk][3], 0.0f));
            Aa[kk][2] = f16x2(fmaxf(Ca[2 * kk + 1][0], 0.0f), fmaxf(Ca[2 * kk + 1][1], 0.0f));
            Aa[kk][3] = f16x2(fmaxf(Ca[2 * kk + 1][2], 0.0f), fmaxf(Ca[2 * kk + 1][3], 0.0f));
            Ab[kk][0] = f16x2(fmaxf(Cb[2 * kk][0], 0.0f),     fmaxf(Cb[2 * kk][1], 0.0f));
            Ab[kk][1] = f16x2(fmaxf(Cb[2 * kk][2], 0.0f),     fmaxf(Cb[2 * kk][3], 0.0f));
            Ab[kk][2] = f16x2(fmaxf(Cb[2 * kk + 1][0], 0.0f), fmaxf(Cb[2 * kk + 1][1], 0.0f));
            Ab[kk][3] = f16x2(fmaxf(Cb[2 * kk + 1][2], 0.0f), fmaxf(Cb[2 * kk + 1][3], 0.0f));
        }

        // ---- layer 1 + W2 as MMA, B fragments shared by both tiles ----
        float C2a[4] = {0.f, 0.f, 0.f, 0.f};
        float C2b[4] = {0.f, 0.f, 0.f, 0.f};
#pragma unroll
        for (int kk2 = 0; kk2 < 4; kk2++) {
            uint32_t A2a[4], A2b[4];
#pragma unroll
            for (int s = 0; s < 2; s++) {
                const int nt = 2 * kk2 + s;
                float C1a[4] = {0.f, 0.f, 0.f, 0.f};
                float C1b[4] = {0.f, 0.f, 0.f, 0.f};
#pragma unroll
                for (int kkp = 0; kkp < 2; kkp++) {
                    const uint4 b = w1q[kkp][nt][lane];
                    mma16(C1a, Aa[2 * kkp][0],     Aa[2 * kkp][1],     Aa[2 * kkp][2],     Aa[2 * kkp][3],     b.x, b.y);
                    mma16(C1a, Aa[2 * kkp + 1][0], Aa[2 * kkp + 1][1], Aa[2 * kkp + 1][2], Aa[2 * kkp + 1][3], b.z, b.w);
                    mma16(C1b, Ab[2 * kkp][0],     Ab[2 * kkp][1],     Ab[2 * kkp][2],     Ab[2 * kkp][3],     b.x, b.y);
                    mma16(C1b, Ab[2 * kkp + 1][0], Ab[2 * kkp + 1][1], Ab[2 * kkp + 1][2], Ab[2 * kkp + 1][3], b.z, b.w);
                }
                A2a[2 * s]     = f16x2(fmaxf(C1a[0], 0.0f), fmaxf(C1a[1], 0.0f));
                A2a[2 * s + 1] = f16x2(fmaxf(C1a[2], 0.0f), fmaxf(C1a[3], 0.0f));
                A2b[2 * s]     = f16x2(fmaxf(C1b[0], 0.0f), fmaxf(C1b[1], 0.0f));
                A2b[2 * s + 1] = f16x2(fmaxf(C1b[2], 0.0f), fmaxf(C1b[3], 0.0f));
            }
            const uint2 b2 = w2f[kk2][lane];
            mma16(C2a, A2a[0], A2a[1], A2a[2], A2a[3], b2.x, b2.y);
            mma16(C2b, A2b[0], A2b[1], A2b[2], A2b[3], b2.x, b2.y);
        }

        // ---- direct stores (cols: t=0 -> j0,j1; t=1 -> j2) ----
        const int tb0 = wg * PPW + (2 * pr) * TILE;
        const int tb1 = tb0 + TILE;
        if (t == 0) {
            out[0 * NPTS + tb0 + g]     = C2a[0] * ESCALE_I;
            out[1 * NPTS + tb0 + g]     = C2a[1] * ESCALE_I;
            out[0 * NPTS + tb0 + g + 8] = C2a[2] * ESCALE_I;
            out[1 * NPTS + tb0 + g + 8] = C2a[3] * ESCALE_I;
            out[0 * NPTS + tb1 + g]     = C2b[0] * ESCALE_I;
            out[1 * NPTS + tb1 + g]     = C2b[1] * ESCALE_I;
            out[0 * NPTS + tb1 + g + 8] = C2b[2] * ESCALE_I;
            out[1 * NPTS + tb1 + g + 8] = C2b[3] * ESCALE_I;
        } else if (t == 1) {
            out[2 * NPTS + tb0 + g]     = C2a[0] * ESCALE_I;
            out[2 * NPTS + tb0 + g + 8] = C2a[2] * ESCALE_I;
            out[2 * NPTS + tb1 + g]     = C2b[0] * ESCALE_I;
            out[2 * NPTS + tb1 + g + 8] = C2b[2] * ESCALE_I;
        }

        __syncwarp();   // buffers fully consumed before next pair overwrites
    }
}

}  // namespace

extern "C" void kernel_launch(void* const* d_in, const int* in_sizes, int n_in,
                              void* d_out, int out_size) {
    (void)in_sizes; (void)n_in; (void)out_size;
    const float2* xy  = (const float2*)d_in[0];
    const float2* tab = (const float2*)d_in[1];
    const float*  W0  = (const float*)d_in[2];
    const float*  W1  = (const float*)d_in[3];
    const float*  W2  = (const float*)d_in[4];
    float* out = (float*)d_out;

    ngp_mma_kernel<<<GRID, THREADS>>>(xy, tab, W0, W1, W2, out);
}